// round 1
// baseline (speedup 1.0000x reference)
#include <cuda_runtime.h>
#include <math.h>

#define B_    8
#define NH    8
#define T_    8
#define HD    32
#define C_    256
#define N_    8192
#define HW    1024
#define W_    32
#define BHT   512            // B*NH*T
#define M_TOT 65536          // B*N

// ---------------- scratch (static device globals; no allocation) ----------------
__device__ float g_qk[(size_t)M_TOT * 512];       // 128 MB : raw qk GEMM output
__device__ float g_qn[(size_t)BHT * HW * HD];     //  64 MB : normalized q, [bht][p][c]
__device__ float g_kn[(size_t)BHT * HD * HW];     //  64 MB : normalized shifted k, [bht][c][p]
__device__ float g_v [(size_t)M_TOT * C_];        //  64 MB : corr-projected v in [B,N,C]

// =================================================================================
// Generic NT SGEMM:  C[m,n] = sum_k A[m,k]*B[n,k] (+ bias[n])
// 128x128 block tile, BK=16, 256 threads, 8x8 per-thread (2x2 of 4x4 quads)
// =================================================================================
#define SLD 132   // padded smem leading stride (floats)

__global__ void __launch_bounds__(256, 2)
sgemm_nt(const float* __restrict__ A, const float* __restrict__ Bm,
         const float* __restrict__ bias, float* __restrict__ Cc,
         int M, int Nc, int K)
{
    __shared__ float As[16 * SLD];
    __shared__ float Bs[16 * SLD];

    const int tid = threadIdx.x;
    const int tx  = tid & 15;       // 0..15
    const int ty  = tid >> 4;       // 0..15
    const int m0  = blockIdx.y * 128;
    const int n0  = blockIdx.x * 128;

    const float* Aptr = A  + (size_t)m0 * K;
    const float* Bptr = Bm + (size_t)n0 * K;

    float acc[8][8];
#pragma unroll
    for (int i = 0; i < 8; i++)
#pragma unroll
        for (int j = 0; j < 8; j++) acc[i][j] = 0.f;

    for (int k0 = 0; k0 < K; k0 += 16) {
        // cooperative load of A,B tiles (128 rows x 16 k) with transpose into smem
#pragma unroll
        for (int rep = 0; rep < 2; rep++) {
            int idx = tid + rep * 256;          // 0..511
            int row = idx >> 2;                 // 0..127
            int c4  = (idx & 3) * 4;            // 0,4,8,12
            float4 va = *(const float4*)(Aptr + (size_t)row * K + k0 + c4);
            As[(c4 + 0) * SLD + row] = va.x;
            As[(c4 + 1) * SLD + row] = va.y;
            As[(c4 + 2) * SLD + row] = va.z;
            As[(c4 + 3) * SLD + row] = va.w;
            float4 vb = *(const float4*)(Bptr + (size_t)row * K + k0 + c4);
            Bs[(c4 + 0) * SLD + row] = vb.x;
            Bs[(c4 + 1) * SLD + row] = vb.y;
            Bs[(c4 + 2) * SLD + row] = vb.z;
            Bs[(c4 + 3) * SLD + row] = vb.w;
        }
        __syncthreads();

#pragma unroll
        for (int k = 0; k < 16; k++) {
            float4 a0 = *(const float4*)&As[k * SLD + ty * 4];
            float4 a1 = *(const float4*)&As[k * SLD + 64 + ty * 4];
            float4 b0 = *(const float4*)&Bs[k * SLD + tx * 4];
            float4 b1 = *(const float4*)&Bs[k * SLD + 64 + tx * 4];
            float a[8] = {a0.x, a0.y, a0.z, a0.w, a1.x, a1.y, a1.z, a1.w};
            float b[8] = {b0.x, b0.y, b0.z, b0.w, b1.x, b1.y, b1.z, b1.w};
#pragma unroll
            for (int i = 0; i < 8; i++)
#pragma unroll
                for (int j = 0; j < 8; j++)
                    acc[i][j] += a[i] * b[j];
        }
        __syncthreads();
    }

    // epilogue
#pragma unroll
    for (int i = 0; i < 8; i++) {
        int mm = m0 + ((i < 4) ? (ty * 4 + i) : (64 + ty * 4 + i - 4));
        float* crow = Cc + (size_t)mm * Nc;
        int c0 = n0 + tx * 4;
        int c1 = n0 + 64 + tx * 4;
        float4 o0, o1;
        o0.x = acc[i][0]; o0.y = acc[i][1]; o0.z = acc[i][2]; o0.w = acc[i][3];
        o1.x = acc[i][4]; o1.y = acc[i][5]; o1.z = acc[i][6]; o1.w = acc[i][7];
        if (bias) {
            o0.x += bias[c0 + 0]; o0.y += bias[c0 + 1]; o0.z += bias[c0 + 2]; o0.w += bias[c0 + 3];
            o1.x += bias[c1 + 0]; o1.y += bias[c1 + 1]; o1.z += bias[c1 + 2]; o1.w += bias[c1 + 3];
        }
        *(float4*)(crow + c0) = o0;
        *(float4*)(crow + c1) = o1;
    }
}

// =================================================================================
// Normalize + relayout.
// One warp handles one pixel's 32-dim vector (lane = channel).
// q -> g_qn [bht][p][c] (channel-last)
// k (temporally shifted, t_src=min(t+1,7)) -> g_kn [bht][c][p] (channel-first,
// via smem transpose for coalesced stores)
// =================================================================================
__global__ void __launch_bounds__(256)
norm_kernel(const float* __restrict__ qk, float* __restrict__ qn, float* __restrict__ kn)
{
    __shared__ float sh[32][33];
    const int tid  = threadIdx.x;
    const int lane = tid & 31;
    const int warp = tid >> 5;

    const int bht   = blockIdx.x >> 5;        // 32 blocks per image
    const int pbase = (blockIdx.x & 31) * 32;
    const int t    = bht & 7;
    const int head = (bht >> 3) & 7;
    const int b    = bht >> 6;
    const int ts   = (t + 1 < 8) ? (t + 1) : 7;

#pragma unroll
    for (int it = 0; it < 4; it++) {
        const int pl = it * 8 + warp;     // 0..31 pixel within block
        const int p  = pbase + pl;
        // ---- q ----
        {
            size_t idx = ((size_t)(b * N_ + t * HW + p)) * 512 + head * 32 + lane;
            float v = qk[idx];
            float ss = v * v;
#pragma unroll
            for (int o = 16; o; o >>= 1) ss += __shfl_xor_sync(0xffffffffu, ss, o);
            v = v / fmaxf(sqrtf(ss), 1e-12f);
            qn[((size_t)bht * HW + p) * 32 + lane] = v;
        }
        // ---- k (shifted frame) ----
        {
            size_t idx = ((size_t)(b * N_ + ts * HW + p)) * 512 + 256 + head * 32 + lane;
            float v = qk[idx];
            float ss = v * v;
#pragma unroll
            for (int o = 16; o; o >>= 1) ss += __shfl_xor_sync(0xffffffffu, ss, o);
            v = v / fmaxf(sqrtf(ss), 1e-12f);
            sh[pl][lane] = v;
        }
    }
    __syncthreads();

    // transpose write: kn[bht][c][pbase + 0..31]
    const int c  = tid >> 3;             // 0..31
    const int p4 = (tid & 7) * 4;        // 0,4,...,28
    float4 o;
    o.x = sh[p4 + 0][c];
    o.y = sh[p4 + 1][c];
    o.z = sh[p4 + 2][c];
    o.w = sh[p4 + 3][c];
    *(float4*)&kn[((size_t)bht * 32 + c) * HW + pbase + p4] = o;
}

// =================================================================================
// Fused 7x7 correlation + (49 -> hd) projection.
// One block per image (bht). Whole 38x38x32 zero-padded k tile in smem
// (channel-first, stride 1445 so rows of 32 lanes are conflict-free).
// Each thread: 4 pixels; per pixel q[32] in regs, accumulate v[32] in regs.
// =================================================================================
#define KS 1445                               // 38*38 = 1444, +1 pad (odd stride)
#define CORR_SMEM_FLOATS (32 * KS + 49 * 32 + 32)
#define CORR_SMEM_BYTES  (CORR_SMEM_FLOATS * 4)

__global__ void __launch_bounds__(256)
corr_kernel(const float* __restrict__ qn, const float* __restrict__ kn,
            const float* __restrict__ wc, const float* __restrict__ bc,
            float* __restrict__ vout)
{
    extern __shared__ float sh[];
    float* shk = sh;                 // 32*1445 : k tile, channel-first, halo=3
    float* shw = sh + 32 * KS;       // 49*32   : w_corr transposed -> wT[j][e]
    float* shb = shw + 49 * 32;      // 32      : b_corr

    const int tid = threadIdx.x;
    const int bht = blockIdx.x;

    for (int i = tid; i < 32 * KS; i += 256) shk[i] = 0.f;
    for (int i = tid; i < 49 * 32; i += 256) {
        int j = i >> 5, e = i & 31;
        shw[i] = wc[e * 49 + j];
    }
    if (tid < 32) shb[tid] = bc[tid];
    __syncthreads();

    // fill interior of k tile
    const float* ksrc = kn + (size_t)bht * 32 * HW;
    for (int i = tid; i < 32 * HW; i += 256) {
        int c = i >> 10, p = i & 1023;
        int py = p >> 5, px = p & 31;
        shk[c * KS + (py + 3) * 38 + (px + 3)] = ksrc[i];
    }
    __syncthreads();

    const int tx = tid & 31;          // x position
    const int ty = tid >> 5;          // 0..7
    const int t    = bht & 7;
    const int head = (bht >> 3) & 7;
    const int b    = bht >> 6;

    for (int it = 0; it < 4; it++) {
        const int y = ty + it * 8;
        const int p = y * 32 + tx;

        float q[32];
        const float4* qv = (const float4*)(qn + ((size_t)bht * HW + p) * 32);
#pragma unroll
        for (int i = 0; i < 8; i++) {
            float4 f = qv[i];
            q[i * 4 + 0] = f.x; q[i * 4 + 1] = f.y;
            q[i * 4 + 2] = f.z; q[i * 4 + 3] = f.w;
        }
        float v[32];
#pragma unroll
        for (int e = 0; e < 32; e++) v[e] = 0.f;

        for (int dy = 0; dy < 7; dy++) {
            const int rb = (y + dy) * 38 + tx;
#pragma unroll
            for (int dx = 0; dx < 7; dx++) {
                const float* kp = shk + rb + dx;
                float corr = 0.f;
#pragma unroll
                for (int c = 0; c < 32; c++) corr += q[c] * kp[c * KS];
                const float4* wv = (const float4*)(shw + (dy * 7 + dx) * 32);
#pragma unroll
                for (int e = 0; e < 8; e++) {
                    float4 ww = wv[e];
                    v[e * 4 + 0] += corr * ww.x;
                    v[e * 4 + 1] += corr * ww.y;
                    v[e * 4 + 2] += corr * ww.z;
                    v[e * 4 + 3] += corr * ww.w;
                }
            }
        }

        float* op = vout + ((size_t)b * N_ + t * HW + p) * C_ + head * 32;
#pragma unroll
        for (int e = 0; e < 8; e++) {
            float4 o;
            o.x = v[e * 4 + 0] + shb[e * 4 + 0];
            o.y = v[e * 4 + 1] + shb[e * 4 + 1];
            o.z = v[e * 4 + 2] + shb[e * 4 + 2];
            o.w = v[e * 4 + 3] + shb[e * 4 + 3];
            *(float4*)(op + e * 4) = o;
        }
    }
}

// =================================================================================
extern "C" void kernel_launch(void* const* d_in, const int* in_sizes, int n_in,
                              void* d_out, int out_size)
{
    const float* x      = (const float*)d_in[0];
    const float* w_qk   = (const float*)d_in[1];
    const float* w_corr = (const float*)d_in[2];
    const float* b_corr = (const float*)d_in[3];
    const float* w_proj = (const float*)d_in[4];
    const float* b_proj = (const float*)d_in[5];
    float* out = (float*)d_out;

    float *qk, *qn, *kn, *v;
    cudaGetSymbolAddress((void**)&qk, g_qk);
    cudaGetSymbolAddress((void**)&qn, g_qn);
    cudaGetSymbolAddress((void**)&kn, g_kn);
    cudaGetSymbolAddress((void**)&v,  g_v);

    // 1) qk = x @ w_qk^T : [65536,512]
    sgemm_nt<<<dim3(512 / 128, M_TOT / 128), 256>>>(x, w_qk, nullptr, qk, M_TOT, 512, 256);

    // 2) normalize + temporal shift + relayout
    norm_kernel<<<BHT * (HW / 32), 256>>>(qk, qn, kn);

    // 3) fused 7x7 correlation + w_corr projection
    static bool attr_done = false;
    cudaFuncSetAttribute(corr_kernel, cudaFuncAttributeMaxDynamicSharedMemorySize,
                         CORR_SMEM_BYTES);
    (void)attr_done;
    corr_kernel<<<BHT, 256, CORR_SMEM_BYTES>>>(qn, kn, w_corr, b_corr, v);

    // 4) out = v @ w_proj^T + b_proj : [65536,256]
    sgemm_nt<<<dim3(256 / 128, M_TOT / 128), 256>>>(v, w_proj, b_proj, out, M_TOT, 256, 256);
}

// round 3
// speedup vs baseline: 1.5586x; 1.5586x over previous
#include <cuda_runtime.h>
#include <cuda_bf16.h>
#include <math.h>
#include <stdint.h>

#define B_    8
#define NH    8
#define T_    8
#define HD    32
#define C_    256
#define N_    8192
#define HW    1024
#define BHT   512            // B*NH*T
#define M_TOT 65536          // B*N

// ---------------- scratch (static device globals; no allocation) ----------------
__device__ float g_qk[(size_t)M_TOT * 512];            // 134 MB : qk GEMM output (fp32)
__device__ float g_qn[(size_t)BHT * HW * HD];          //  67 MB : normalized q [bht][p][c]
__device__ float g_kn[(size_t)BHT * HD * HW];          //  67 MB : normalized shifted k [bht][c][p]
__device__ __nv_bfloat16 g_xhi[(size_t)M_TOT * C_];    //  34 MB
__device__ __nv_bfloat16 g_xlo[(size_t)M_TOT * C_];
__device__ __nv_bfloat16 g_vhi[(size_t)M_TOT * C_];
__device__ __nv_bfloat16 g_vlo[(size_t)M_TOT * C_];
__device__ __nv_bfloat16 g_wqk_hi[512 * 256];
__device__ __nv_bfloat16 g_wqk_lo[512 * 256];
__device__ __nv_bfloat16 g_wpj_hi[256 * 256];
__device__ __nv_bfloat16 g_wpj_lo[256 * 256];

// ======================= asm helpers (sm_80-base features only) ==================
__device__ __forceinline__ uint32_t smem_u32(const void* p) {
    uint32_t a;
    asm("{ .reg .u64 t; cvta.to.shared.u64 t, %1; cvt.u32.u64 %0, t; }" : "=r"(a) : "l"(p));
    return a;
}
__device__ __forceinline__ void cp16(uint32_t saddr, const void* g) {
    asm volatile("cp.async.cg.shared.global [%0], [%1], 16;" :: "r"(saddr), "l"(g));
}
#define CP_COMMIT() asm volatile("cp.async.commit_group;" ::: "memory")
#define CP_WAIT0()  asm volatile("cp.async.wait_group 0;" ::: "memory")

#define LDSM4(r0, r1, r2, r3, addr) \
    asm volatile("ldmatrix.sync.aligned.m8n8.x4.shared.b16 {%0,%1,%2,%3}, [%4];" \
                 : "=r"(r0), "=r"(r1), "=r"(r2), "=r"(r3) : "r"(addr))
#define LDSM2(r0, r1, addr) \
    asm volatile("ldmatrix.sync.aligned.m8n8.x2.shared.b16 {%0,%1}, [%2];" \
                 : "=r"(r0), "=r"(r1) : "r"(addr))
#define MMA16816(c, a, b) \
    asm volatile("mma.sync.aligned.m16n8k16.row.col.f32.bf16.bf16.f32 " \
                 "{%0,%1,%2,%3},{%4,%5,%6,%7},{%8,%9},{%0,%1,%2,%3};" \
                 : "+f"((c)[0]), "+f"((c)[1]), "+f"((c)[2]), "+f"((c)[3]) \
                 : "r"((a)[0]), "r"((a)[1]), "r"((a)[2]), "r"((a)[3]), \
                   "r"((b)[0]), "r"((b)[1]))

// =================================================================================
// fp32 -> (bf16 hi, bf16 lo) split, vectorized
// =================================================================================
__global__ void __launch_bounds__(256)
conv_split(const float4* __restrict__ in, uint2* __restrict__ hi,
           uint2* __restrict__ lo, int n4)
{
    int i = blockIdx.x * 256 + threadIdx.x;
    if (i >= n4) return;
    float4 f = in[i];
    __nv_bfloat162 h0 = __floats2bfloat162_rn(f.x, f.y);
    __nv_bfloat162 h1 = __floats2bfloat162_rn(f.z, f.w);
    float r0 = f.x - __bfloat162float(__low2bfloat16(h0));
    float r1 = f.y - __bfloat162float(__high2bfloat16(h0));
    float r2 = f.z - __bfloat162float(__low2bfloat16(h1));
    float r3 = f.w - __bfloat162float(__high2bfloat16(h1));
    __nv_bfloat162 l0 = __floats2bfloat162_rn(r0, r1);
    __nv_bfloat162 l1 = __floats2bfloat162_rn(r2, r3);
    hi[i] = make_uint2(*(uint32_t*)&h0, *(uint32_t*)&h1);
    lo[i] = make_uint2(*(uint32_t*)&l0, *(uint32_t*)&l1);
}

// =================================================================================
// bf16 3-term mma.sync GEMM (NT): C[m,n] = sum_k A[m,k]*B[n,k] (+bias[n]), fp32 out
// block 128x128, 256 thr (8 warps, 2m x 4n grid, warp tile 64x32), k-tile 32,
// 2-stage cp.async pipeline.  smem stage: Ahi|Alo|Bhi|Blo, 8KB each.
// =================================================================================
#define GM_STAGE 32768
#define GM_SMEM  (2 * GM_STAGE)

__device__ __forceinline__ void stage_load(
    uint32_t sbase, const __nv_bfloat16* __restrict__ Ahi,
    const __nv_bfloat16* __restrict__ Alo, const __nv_bfloat16* __restrict__ Bhi,
    const __nv_bfloat16* __restrict__ Blo, int m0, int n0, int K, int kt, int tid)
{
    int t = tid * 2;
    int row = t >> 2;
    int cb  = t & 3;
#pragma unroll
    for (int j = 0; j < 2; j++) {
        int c16 = cb + j;
        uint32_t soff = (uint32_t)(row * 64 + ((c16 ^ ((row >> 1) & 3)) << 4));
        size_t ga = (size_t)row * K + kt * 32 + c16 * 8;   // element offset
        cp16(sbase +     0 + soff, Ahi + (size_t)m0 * K + ga);
        cp16(sbase +  8192 + soff, Alo + (size_t)m0 * K + ga);
        cp16(sbase + 16384 + soff, Bhi + (size_t)n0 * K + ga);
        cp16(sbase + 24576 + soff, Blo + (size_t)n0 * K + ga);
    }
}

__global__ void __launch_bounds__(256, 2)
gemm_bf16x3(const __nv_bfloat16* __restrict__ Ahi, const __nv_bfloat16* __restrict__ Alo,
            const __nv_bfloat16* __restrict__ Bhi, const __nv_bfloat16* __restrict__ Blo,
            const float* __restrict__ bias, float* __restrict__ C, int K, int ldc)
{
    extern __shared__ char smg[];
    const uint32_t sb = smem_u32(smg);
    const int tid = threadIdx.x;
    const int lane = tid & 31;
    const int wid = tid >> 5;
    const int m0 = blockIdx.y * 128;
    const int n0 = blockIdx.x * 128;
    const int wm = (wid >> 2) * 64;
    const int wn = (wid & 3) * 32;
    const int NT = K >> 5;

    float acc[4][4][4];
#pragma unroll
    for (int i = 0; i < 4; i++)
#pragma unroll
        for (int j = 0; j < 4; j++)
#pragma unroll
            for (int q = 0; q < 4; q++) acc[i][j][q] = 0.f;

    stage_load(sb, Ahi, Alo, Bhi, Blo, m0, n0, K, 0, tid);
    CP_COMMIT();

    for (int kt = 0; kt < NT; kt++) {
        CP_WAIT0();
        __syncthreads();
        if (kt + 1 < NT)
            stage_load(sb + ((kt + 1) & 1) * GM_STAGE, Ahi, Alo, Bhi, Blo,
                       m0, n0, K, kt + 1, tid);
        CP_COMMIT();

        const uint32_t sa = sb + (kt & 1) * GM_STAGE;
#pragma unroll
        for (int ks = 0; ks < 2; ks++) {
            const uint32_t l2 = lane & 15;
            uint32_t aaddr[4], baddr[4];
            {
                uint32_t achk = (uint32_t)(ks * 2) + (lane >> 4);
#pragma unroll
                for (int i = 0; i < 4; i++) {
                    uint32_t r = wm + l2 + i * 16;
                    aaddr[i] = sa + r * 64 + ((achk ^ ((r >> 1) & 3)) << 4);
                }
                uint32_t bchk = (uint32_t)(ks * 2) + ((l2 >> 3) & 1);
#pragma unroll
                for (int j = 0; j < 4; j++) {
                    uint32_t r = wn + (l2 & 7) + j * 8;
                    baddr[j] = sa + 16384 + r * 64 + ((bchk ^ ((r >> 1) & 3)) << 4);
                }
            }
            uint32_t a[4][4], b[4][2];
            // term 1: Ahi * Bhi
#pragma unroll
            for (int i = 0; i < 4; i++) LDSM4(a[i][0], a[i][1], a[i][2], a[i][3], aaddr[i]);
#pragma unroll
            for (int j = 0; j < 4; j++) LDSM2(b[j][0], b[j][1], baddr[j]);
#pragma unroll
            for (int i = 0; i < 4; i++)
#pragma unroll
                for (int j = 0; j < 4; j++) MMA16816(acc[i][j], a[i], b[j]);
            // term 2: Alo * Bhi
#pragma unroll
            for (int i = 0; i < 4; i++) LDSM4(a[i][0], a[i][1], a[i][2], a[i][3], aaddr[i] + 8192);
#pragma unroll
            for (int i = 0; i < 4; i++)
#pragma unroll
                for (int j = 0; j < 4; j++) MMA16816(acc[i][j], a[i], b[j]);
            // term 3: Ahi * Blo
#pragma unroll
            for (int j = 0; j < 4; j++) LDSM2(b[j][0], b[j][1], baddr[j] + 8192);
#pragma unroll
            for (int i = 0; i < 4; i++) LDSM4(a[i][0], a[i][1], a[i][2], a[i][3], aaddr[i]);
#pragma unroll
            for (int i = 0; i < 4; i++)
#pragma unroll
                for (int j = 0; j < 4; j++) MMA16816(acc[i][j], a[i], b[j]);
        }
    }

    // epilogue
#pragma unroll
    for (int j = 0; j < 4; j++) {
        int c = n0 + wn + j * 8 + (lane & 3) * 2;
        float b0 = 0.f, b1 = 0.f;
        if (bias) { b0 = bias[c]; b1 = bias[c + 1]; }
#pragma unroll
        for (int i = 0; i < 4; i++) {
            int r = m0 + wm + i * 16 + (lane >> 2);
            float2 o0 = make_float2(acc[i][j][0] + b0, acc[i][j][1] + b1);
            float2 o1 = make_float2(acc[i][j][2] + b0, acc[i][j][3] + b1);
            *(float2*)(C + (size_t)r * ldc + c)       = o0;
            *(float2*)(C + (size_t)(r + 8) * ldc + c) = o1;
        }
    }
}

// =================================================================================
// Normalize + temporal shift + relayout (unchanged, proven correct)
// =================================================================================
__global__ void __launch_bounds__(256)
norm_kernel(const float* __restrict__ qk, float* __restrict__ qn, float* __restrict__ kn)
{
    __shared__ float sh[32][33];
    const int tid  = threadIdx.x;
    const int lane = tid & 31;
    const int warp = tid >> 5;

    const int bht   = blockIdx.x >> 5;
    const int pbase = (blockIdx.x & 31) * 32;
    const int t    = bht & 7;
    const int head = (bht >> 3) & 7;
    const int b    = bht >> 6;
    const int ts   = (t + 1 < 8) ? (t + 1) : 7;

#pragma unroll
    for (int it = 0; it < 4; it++) {
        const int pl = it * 8 + warp;
        const int p  = pbase + pl;
        {
            size_t idx = ((size_t)(b * N_ + t * HW + p)) * 512 + head * 32 + lane;
            float v = qk[idx];
            float ss = v * v;
#pragma unroll
            for (int o = 16; o; o >>= 1) ss += __shfl_xor_sync(0xffffffffu, ss, o);
            v = v / fmaxf(sqrtf(ss), 1e-12f);
            qn[((size_t)bht * HW + p) * 32 + lane] = v;
        }
        {
            size_t idx = ((size_t)(b * N_ + ts * HW + p)) * 512 + 256 + head * 32 + lane;
            float v = qk[idx];
            float ss = v * v;
#pragma unroll
            for (int o = 16; o; o >>= 1) ss += __shfl_xor_sync(0xffffffffu, ss, o);
            v = v / fmaxf(sqrtf(ss), 1e-12f);
            sh[pl][lane] = v;
        }
    }
    __syncthreads();

    const int c  = tid >> 3;
    const int p4 = (tid & 7) * 4;
    float4 o;
    o.x = sh[p4 + 0][c];
    o.y = sh[p4 + 1][c];
    o.z = sh[p4 + 2][c];
    o.w = sh[p4 + 3][c];
    *(float4*)&kn[((size_t)bht * 32 + c) * HW + pbase + p4] = o;
}

// =================================================================================
// Fused 7x7 correlation + (49->32) projection, quarter-image tiles for occupancy.
// Block = 8 image rows (256 px, 1 px/thread). k tile: 32ch x 14 rows x 38 cols.
// Emits v as bf16 hi/lo (feeds GEMM4 directly).
// =================================================================================
#define KROW 38
#define KCH  (14 * KROW)            // 532 floats per channel
#define CORR_SMEM_FLOATS (32 * KCH + 49 * 32 + 32)
#define CORR_SMEM_BYTES  (CORR_SMEM_FLOATS * 4)

__global__ void __launch_bounds__(256, 3)
corr_kernel(const float* __restrict__ qn, const float* __restrict__ kn,
            const float* __restrict__ wc, const float* __restrict__ bc,
            __nv_bfloat16* __restrict__ vhi, __nv_bfloat16* __restrict__ vlo)
{
    extern __shared__ float sh[];
    float* shk = sh;                    // 32*532
    float* shw = sh + 32 * KCH;         // 49*32 (wT[j][e])
    float* shb = shw + 49 * 32;         // 32

    const int tid = threadIdx.x;
    const int img = blockIdx.x >> 2;
    const int y0  = (blockIdx.x & 3) * 8;

    // zero whole k tile (covers halo + out-of-range rows)
    for (int i = tid; i < (32 * KCH) / 4; i += 256) ((float4*)shk)[i] = make_float4(0, 0, 0, 0);
    for (int i = tid; i < 49 * 32; i += 256) {
        int j = i >> 5, e = i & 31;
        shw[i] = wc[e * 49 + j];
    }
    if (tid < 32) shb[tid] = bc[tid];
    __syncthreads();

    // fill valid k rows: local row r (0..13) <-> global row y0-3+r
    const float* ksrc = kn + (size_t)img * 32 * HW;
    for (int i = tid; i < 32 * 14 * 8; i += 256) {
        int c = i / 112;
        int rem = i - c * 112;
        int r  = rem >> 3;
        int f4 = rem & 7;
        int gy = y0 - 3 + r;
        if (gy >= 0 && gy < 32) {
            float4 val = *(const float4*)(ksrc + (size_t)c * HW + gy * 32 + f4 * 4);
            float* dst = shk + c * KCH + r * KROW + 3 + f4 * 4;
            dst[0] = val.x; dst[1] = val.y; dst[2] = val.z; dst[3] = val.w;
        }
    }
    __syncthreads();

    const int tx = tid & 31;
    const int ty = tid >> 5;
    const int y  = y0 + ty;
    const int p  = y * 32 + tx;
    const int t    = img & 7;
    const int head = (img >> 3) & 7;
    const int b    = img >> 6;

    float q[32];
    {
        const float4* qv = (const float4*)(qn + ((size_t)img * HW + p) * 32);
#pragma unroll
        for (int i = 0; i < 8; i++) {
            float4 f = qv[i];
            q[i * 4 + 0] = f.x; q[i * 4 + 1] = f.y;
            q[i * 4 + 2] = f.z; q[i * 4 + 3] = f.w;
        }
    }
    float v[32];
#pragma unroll
    for (int e = 0; e < 32; e++) v[e] = 0.f;

    for (int dy = 0; dy < 7; dy++) {
        const int rb = (ty + dy) * KROW + tx;
#pragma unroll
        for (int dx = 0; dx < 7; dx++) {
            const float* kp = shk + rb + dx;
            float corr = 0.f;
#pragma unroll
            for (int c = 0; c < 32; c++) corr += q[c] * kp[c * KCH];
            const float4* wv = (const float4*)(shw + (dy * 7 + dx) * 32);
#pragma unroll
            for (int e = 0; e < 8; e++) {
                float4 ww = wv[e];
                v[e * 4 + 0] += corr * ww.x;
                v[e * 4 + 1] += corr * ww.y;
                v[e * 4 + 2] += corr * ww.z;
                v[e * 4 + 3] += corr * ww.w;
            }
        }
    }

    // split to bf16 hi/lo and store
    size_t base = ((size_t)b * N_ + t * HW + p) * C_ + head * 32;
    uint32_t hw[16], lw[16];
#pragma unroll
    for (int e2 = 0; e2 < 16; e2++) {
        float o0 = v[2 * e2 + 0] + shb[2 * e2 + 0];
        float o1 = v[2 * e2 + 1] + shb[2 * e2 + 1];
        __nv_bfloat162 hb = __floats2bfloat162_rn(o0, o1);
        float r0 = o0 - __bfloat162float(__low2bfloat16(hb));
        float r1 = o1 - __bfloat162float(__high2bfloat16(hb));
        __nv_bfloat162 lb = __floats2bfloat162_rn(r0, r1);
        hw[e2] = *(uint32_t*)&hb;
        lw[e2] = *(uint32_t*)&lb;
    }
#pragma unroll
    for (int s = 0; s < 4; s++) {
        *(uint4*)(vhi + base + s * 8) = make_uint4(hw[4*s], hw[4*s+1], hw[4*s+2], hw[4*s+3]);
        *(uint4*)(vlo + base + s * 8) = make_uint4(lw[4*s], lw[4*s+1], lw[4*s+2], lw[4*s+3]);
    }
}

// =================================================================================
extern "C" void kernel_launch(void* const* d_in, const int* in_sizes, int n_in,
                              void* d_out, int out_size)
{
    const float* x      = (const float*)d_in[0];
    const float* w_qk   = (const float*)d_in[1];
    const float* w_corr = (const float*)d_in[2];
    const float* b_corr = (const float*)d_in[3];
    const float* w_proj = (const float*)d_in[4];
    const float* b_proj = (const float*)d_in[5];
    float* out = (float*)d_out;

    float *qk, *qn, *kn;
    __nv_bfloat16 *xhi, *xlo, *vhi, *vlo, *wqh, *wql, *wph, *wpl;
    cudaGetSymbolAddress((void**)&qk,  g_qk);
    cudaGetSymbolAddress((void**)&qn,  g_qn);
    cudaGetSymbolAddress((void**)&kn,  g_kn);
    cudaGetSymbolAddress((void**)&xhi, g_xhi);
    cudaGetSymbolAddress((void**)&xlo, g_xlo);
    cudaGetSymbolAddress((void**)&vhi, g_vhi);
    cudaGetSymbolAddress((void**)&vlo, g_vlo);
    cudaGetSymbolAddress((void**)&wqh, g_wqk_hi);
    cudaGetSymbolAddress((void**)&wql, g_wqk_lo);
    cudaGetSymbolAddress((void**)&wph, g_wpj_hi);
    cudaGetSymbolAddress((void**)&wpl, g_wpj_lo);

    cudaFuncSetAttribute(gemm_bf16x3, cudaFuncAttributeMaxDynamicSharedMemorySize, GM_SMEM);
    cudaFuncSetAttribute(corr_kernel, cudaFuncAttributeMaxDynamicSharedMemorySize,
                         CORR_SMEM_BYTES);

    // 0) hi/lo splits
    conv_split<<<(M_TOT * C_ / 4 + 255) / 256, 256>>>((const float4*)x, (uint2*)xhi, (uint2*)xlo, M_TOT * C_ / 4);
    conv_split<<<(512 * 256 / 4 + 255) / 256, 256>>>((const float4*)w_qk, (uint2*)wqh, (uint2*)wql, 512 * 256 / 4);
    conv_split<<<(256 * 256 / 4 + 255) / 256, 256>>>((const float4*)w_proj, (uint2*)wph, (uint2*)wpl, 256 * 256 / 4);

    // 1) qk = x @ w_qk^T : [65536, 512]
    gemm_bf16x3<<<dim3(4, 512), 256, GM_SMEM>>>(xhi, xlo, wqh, wql, nullptr, qk, 256, 512);

    // 2) normalize + temporal shift + relayout
    norm_kernel<<<BHT * (HW / 32), 256>>>(qk, qn, kn);

    // 3) fused 7x7 correlation + w_corr projection  -> v (bf16 hi/lo)
    corr_kernel<<<BHT * 4, 256, CORR_SMEM_BYTES>>>(qn, kn, w_corr, b_corr, vhi, vlo);

    // 4) out = v @ w_proj^T + b_proj : [65536, 256]
    gemm_bf16x3<<<dim3(2, 512), 256, GM_SMEM>>>(vhi, vlo, wph, wpl, b_proj, out, 256, 256);
}

// round 4
// speedup vs baseline: 1.8163x; 1.1653x over previous
#include <cuda_runtime.h>
#include <cuda_bf16.h>
#include <math.h>
#include <stdint.h>

#define B_    8
#define NH    8
#define T_    8
#define HD    32
#define C_    256
#define N_    8192
#define HW    1024
#define BHT   512            // B*NH*T
#define M_TOT 65536          // B*N

// ---------------- scratch (static device globals; no allocation) ----------------
__device__ float g_qn[(size_t)BHT * HW * HD];          //  67 MB : normalized q [bht][p][c]
__device__ float g_kn[(size_t)BHT * HD * HW];          //  67 MB : normalized shifted k [bht][c][p]
__device__ __nv_bfloat16 g_xhi[(size_t)M_TOT * C_];    //  34 MB
__device__ __nv_bfloat16 g_xlo[(size_t)M_TOT * C_];
__device__ __nv_bfloat16 g_vhi[(size_t)M_TOT * C_];
__device__ __nv_bfloat16 g_vlo[(size_t)M_TOT * C_];
__device__ __nv_bfloat16 g_wqk_hi[512 * 256];
__device__ __nv_bfloat16 g_wqk_lo[512 * 256];
__device__ __nv_bfloat16 g_wpj_hi[256 * 256];
__device__ __nv_bfloat16 g_wpj_lo[256 * 256];

// ======================= asm helpers (sm_80-base features only) ==================
__device__ __forceinline__ uint32_t smem_u32(const void* p) {
    uint32_t a;
    asm("{ .reg .u64 t; cvta.to.shared.u64 t, %1; cvt.u32.u64 %0, t; }" : "=r"(a) : "l"(p));
    return a;
}
__device__ __forceinline__ void cp16(uint32_t saddr, const void* g) {
    asm volatile("cp.async.cg.shared.global [%0], [%1], 16;" :: "r"(saddr), "l"(g));
}
#define CP_COMMIT() asm volatile("cp.async.commit_group;" ::: "memory")
#define CP_WAIT1()  asm volatile("cp.async.wait_group 1;" ::: "memory")

#define LDSM4(r0, r1, r2, r3, addr) \
    asm volatile("ldmatrix.sync.aligned.m8n8.x4.shared.b16 {%0,%1,%2,%3}, [%4];" \
                 : "=r"(r0), "=r"(r1), "=r"(r2), "=r"(r3) : "r"(addr))
#define LDSM2(r0, r1, addr) \
    asm volatile("ldmatrix.sync.aligned.m8n8.x2.shared.b16 {%0,%1}, [%2];" \
                 : "=r"(r0), "=r"(r1) : "r"(addr))
#define MMA16816(c, a, b) \
    asm volatile("mma.sync.aligned.m16n8k16.row.col.f32.bf16.bf16.f32 " \
                 "{%0,%1,%2,%3},{%4,%5,%6,%7},{%8,%9},{%0,%1,%2,%3};" \
                 : "+f"((c)[0]), "+f"((c)[1]), "+f"((c)[2]), "+f"((c)[3]) \
                 : "r"((a)[0]), "r"((a)[1]), "r"((a)[2]), "r"((a)[3]), \
                   "r"((b)[0]), "r"((b)[1]))

// =================================================================================
// fp32 -> (bf16 hi, bf16 lo) split, vectorized
// =================================================================================
__global__ void __launch_bounds__(256)
conv_split(const float4* __restrict__ in, uint2* __restrict__ hi,
           uint2* __restrict__ lo, int n4)
{
    int i = blockIdx.x * 256 + threadIdx.x;
    if (i >= n4) return;
    float4 f = in[i];
    __nv_bfloat162 h0 = __floats2bfloat162_rn(f.x, f.y);
    __nv_bfloat162 h1 = __floats2bfloat162_rn(f.z, f.w);
    float r0 = f.x - __bfloat162float(__low2bfloat16(h0));
    float r1 = f.y - __bfloat162float(__high2bfloat16(h0));
    float r2 = f.z - __bfloat162float(__low2bfloat16(h1));
    float r3 = f.w - __bfloat162float(__high2bfloat16(h1));
    __nv_bfloat162 l0 = __floats2bfloat162_rn(r0, r1);
    __nv_bfloat162 l1 = __floats2bfloat162_rn(r2, r3);
    hi[i] = make_uint2(*(uint32_t*)&h0, *(uint32_t*)&h1);
    lo[i] = make_uint2(*(uint32_t*)&l0, *(uint32_t*)&l1);
}

// =================================================================================
// Shared GEMM machinery: block 128x128, 256 thr, warp tile 64x32, BK=32,
// 3-stage cp.async pipeline, K=256 fixed (NT=8). 3-term bf16 with A-frag reuse.
// =================================================================================
#define KGEMM 256
#define NTILES 8
#define GM_STAGE 32768
#define GM_SMEM  (3 * GM_STAGE)

__device__ __forceinline__ void stage_load(
    uint32_t sbase, const __nv_bfloat16* __restrict__ Ahi,
    const __nv_bfloat16* __restrict__ Alo, const __nv_bfloat16* __restrict__ Bhi,
    const __nv_bfloat16* __restrict__ Blo, int m0, int n0, int kt, int tid)
{
    int t = tid * 2;
    int row = t >> 2;
    int cb  = t & 3;
#pragma unroll
    for (int j = 0; j < 2; j++) {
        int c16 = cb + j;
        uint32_t soff = (uint32_t)(row * 64 + ((c16 ^ ((row >> 1) & 3)) << 4));
        size_t ga = (size_t)row * KGEMM + kt * 32 + c16 * 8;
        cp16(sbase +     0 + soff, Ahi + (size_t)m0 * KGEMM + ga);
        cp16(sbase +  8192 + soff, Alo + (size_t)m0 * KGEMM + ga);
        cp16(sbase + 16384 + soff, Bhi + (size_t)n0 * KGEMM + ga);
        cp16(sbase + 24576 + soff, Blo + (size_t)n0 * KGEMM + ga);
    }
}

// mainloop producing acc[4][4][4]; caller handles epilogue.
__device__ __forceinline__ void gemm_mainloop(
    const __nv_bfloat16* __restrict__ Ahi, const __nv_bfloat16* __restrict__ Alo,
    const __nv_bfloat16* __restrict__ Bhi, const __nv_bfloat16* __restrict__ Blo,
    uint32_t sb, int m0, int n0, int tid, int lane, int wm, int wn,
    float acc[4][4][4])
{
#pragma unroll
    for (int i = 0; i < 4; i++)
#pragma unroll
        for (int j = 0; j < 4; j++)
#pragma unroll
            for (int q = 0; q < 4; q++) acc[i][j][q] = 0.f;

    stage_load(sb,            Ahi, Alo, Bhi, Blo, m0, n0, 0, tid);
    CP_COMMIT();
    stage_load(sb + GM_STAGE, Ahi, Alo, Bhi, Blo, m0, n0, 1, tid);
    CP_COMMIT();

    int stage = 0;        // stage holding tile kt
    int lstage = 2;       // stage to load into next
    for (int kt = 0; kt < NTILES; kt++) {
        CP_WAIT1();
        __syncthreads();
        if (kt + 2 < NTILES)
            stage_load(sb + lstage * GM_STAGE, Ahi, Alo, Bhi, Blo, m0, n0, kt + 2, tid);
        CP_COMMIT();
        lstage = stage;   // this stage becomes free after this iteration's compute

        const uint32_t sa = sb + stage * GM_STAGE;
        stage = (stage == 2) ? 0 : stage + 1;

#pragma unroll
        for (int ks = 0; ks < 2; ks++) {
            const uint32_t l2 = lane & 15;
            uint32_t aaddr[4], baddr[4];
            {
                uint32_t achk = (uint32_t)(ks * 2) + (lane >> 4);
#pragma unroll
                for (int i = 0; i < 4; i++) {
                    uint32_t r = wm + l2 + i * 16;
                    aaddr[i] = sa + r * 64 + ((achk ^ ((r >> 1) & 3)) << 4);
                }
                uint32_t bchk = (uint32_t)(ks * 2) + ((l2 >> 3) & 1);
#pragma unroll
                for (int j = 0; j < 4; j++) {
                    uint32_t r = wn + (l2 & 7) + j * 8;
                    baddr[j] = sa + 16384 + r * 64 + ((bchk ^ ((r >> 1) & 3)) << 4);
                }
            }
            uint32_t a[4][4], bh[4][2], bl[4][2];
#pragma unroll
            for (int i = 0; i < 4; i++) LDSM4(a[i][0], a[i][1], a[i][2], a[i][3], aaddr[i]);
#pragma unroll
            for (int j = 0; j < 4; j++) LDSM2(bh[j][0], bh[j][1], baddr[j]);
#pragma unroll
            for (int j = 0; j < 4; j++) LDSM2(bl[j][0], bl[j][1], baddr[j] + 8192);
            // term 1: Ahi*Bhi
#pragma unroll
            for (int i = 0; i < 4; i++)
#pragma unroll
                for (int j = 0; j < 4; j++) MMA16816(acc[i][j], a[i], bh[j]);
            // term 3: Ahi*Blo (reuse a regs)
#pragma unroll
            for (int i = 0; i < 4; i++)
#pragma unroll
                for (int j = 0; j < 4; j++) MMA16816(acc[i][j], a[i], bl[j]);
            // term 2: Alo*Bhi
#pragma unroll
            for (int i = 0; i < 4; i++) LDSM4(a[i][0], a[i][1], a[i][2], a[i][3], aaddr[i] + 8192);
#pragma unroll
            for (int i = 0; i < 4; i++)
#pragma unroll
                for (int j = 0; j < 4; j++) MMA16816(acc[i][j], a[i], bh[j]);
        }
    }
}

// =================================================================================
// GEMM1 fused: qk = x @ w_qk^T, then per-(row,head) L2-normalize + temporal shift,
// writing qn (channel-last) and kn (channel-first, shifted). No qk materialized.
// grid: dim3(4, 512); blockIdx.x 0,1 -> q cols [0,256); 2,3 -> k cols [256,512)
// =================================================================================
__global__ void __launch_bounds__(256, 2)
gemm_qk(const __nv_bfloat16* __restrict__ Ahi, const __nv_bfloat16* __restrict__ Alo,
        const __nv_bfloat16* __restrict__ Bhi, const __nv_bfloat16* __restrict__ Blo,
        float* __restrict__ qn, float* __restrict__ kn)
{
    extern __shared__ char smg[];
    const uint32_t sb = smem_u32(smg);
    const int tid = threadIdx.x;
    const int lane = tid & 31;
    const int wid = tid >> 5;
    const int m0 = blockIdx.y * 128;
    const int n0 = blockIdx.x * 128;
    const int wm = (wid >> 2) * 64;
    const int wn = (wid & 3) * 32;

    float acc[4][4][4];
    gemm_mainloop(Ahi, Alo, Bhi, Blo, sb, m0, n0, tid, lane, wm, wn, acc);

    const bool is_k = (blockIdx.x >= 2);
    const int head = (((n0 & 255) + wn) >> 5);   // 0..7

#pragma unroll
    for (int i = 0; i < 4; i++) {
#pragma unroll
        for (int h = 0; h < 2; h++) {
            float v0[4], v1[4];
            float ss = 0.f;
#pragma unroll
            for (int j = 0; j < 4; j++) {
                v0[j] = acc[i][j][2 * h];
                v1[j] = acc[i][j][2 * h + 1];
                ss += v0[j] * v0[j] + v1[j] * v1[j];
            }
            ss += __shfl_xor_sync(0xffffffffu, ss, 1);
            ss += __shfl_xor_sync(0xffffffffu, ss, 2);
            float inv = 1.0f / fmaxf(sqrtf(ss), 1e-12f);

            int r = m0 + wm + i * 16 + (lane >> 2) + h * 8;
            int b  = r >> 13;
            int tt = (r >> 10) & 7;
            int p  = r & 1023;

            if (!is_k) {
                int bht = b * 64 + head * 8 + tt;
                float* dst = qn + ((size_t)bht * HW + p) * 32;
#pragma unroll
                for (int j = 0; j < 4; j++) {
                    int cin = j * 8 + (lane & 3) * 2;
                    *(float2*)(dst + cin) = make_float2(v0[j] * inv, v1[j] * inv);
                }
            } else {
                // source frame tt feeds dst t = tt-1; frame 7 also feeds t = 7
                if (tt >= 1) {
                    int bht = b * 64 + head * 8 + (tt - 1);
                    float* dst = kn + (size_t)bht * 32 * HW + p;
#pragma unroll
                    for (int j = 0; j < 4; j++) {
                        int cin = j * 8 + (lane & 3) * 2;
                        dst[(size_t)cin * HW]       = v0[j] * inv;
                        dst[(size_t)(cin + 1) * HW] = v1[j] * inv;
                    }
                }
                if (tt == 7) {
                    int bht = b * 64 + head * 8 + 7;
                    float* dst = kn + (size_t)bht * 32 * HW + p;
#pragma unroll
                    for (int j = 0; j < 4; j++) {
                        int cin = j * 8 + (lane & 3) * 2;
                        dst[(size_t)cin * HW]       = v0[j] * inv;
                        dst[(size_t)(cin + 1) * HW] = v1[j] * inv;
                    }
                }
            }
        }
    }
}

// =================================================================================
// GEMM4: out = v @ w_proj^T + bias, fp32 out
// =================================================================================
__global__ void __launch_bounds__(256, 2)
gemm_proj(const __nv_bfloat16* __restrict__ Ahi, const __nv_bfloat16* __restrict__ Alo,
          const __nv_bfloat16* __restrict__ Bhi, const __nv_bfloat16* __restrict__ Blo,
          const float* __restrict__ bias, float* __restrict__ C, int ldc)
{
    extern __shared__ char smg[];
    const uint32_t sb = smem_u32(smg);
    const int tid = threadIdx.x;
    const int lane = tid & 31;
    const int wid = tid >> 5;
    const int m0 = blockIdx.y * 128;
    const int n0 = blockIdx.x * 128;
    const int wm = (wid >> 2) * 64;
    const int wn = (wid & 3) * 32;

    float acc[4][4][4];
    gemm_mainloop(Ahi, Alo, Bhi, Blo, sb, m0, n0, tid, lane, wm, wn, acc);

#pragma unroll
    for (int j = 0; j < 4; j++) {
        int c = n0 + wn + j * 8 + (lane & 3) * 2;
        float b0 = bias[c], b1 = bias[c + 1];
#pragma unroll
        for (int i = 0; i < 4; i++) {
            int r = m0 + wm + i * 16 + (lane >> 2);
            *(float2*)(C + (size_t)r * ldc + c) =
                make_float2(acc[i][j][0] + b0, acc[i][j][1] + b1);
            *(float2*)(C + (size_t)(r + 8) * ldc + c) =
                make_float2(acc[i][j][2] + b0, acc[i][j][3] + b1);
        }
    }
}

// =================================================================================
// Fused 7x7 correlation + (49->32) projection, quarter-image tiles.
// Emits v as bf16 hi/lo (feeds GEMM4 directly).
// =================================================================================
#define KROW 38
#define KCH  (14 * KROW)            // 532 floats per channel
#define CORR_SMEM_FLOATS (32 * KCH + 49 * 32 + 32)
#define CORR_SMEM_BYTES  (CORR_SMEM_FLOATS * 4)

__global__ void __launch_bounds__(256, 3)
corr_kernel(const float* __restrict__ qn, const float* __restrict__ kn,
            const float* __restrict__ wc, const float* __restrict__ bc,
            __nv_bfloat16* __restrict__ vhi, __nv_bfloat16* __restrict__ vlo)
{
    extern __shared__ float sh[];
    float* shk = sh;                    // 32*532
    float* shw = sh + 32 * KCH;         // 49*32 (wT[j][e])
    float* shb = shw + 49 * 32;         // 32

    const int tid = threadIdx.x;
    const int img = blockIdx.x >> 2;
    const int y0  = (blockIdx.x & 3) * 8;

    for (int i = tid; i < (32 * KCH) / 4; i += 256) ((float4*)shk)[i] = make_float4(0, 0, 0, 0);
    for (int i = tid; i < 49 * 32; i += 256) {
        int j = i >> 5, e = i & 31;
        shw[i] = wc[e * 49 + j];
    }
    if (tid < 32) shb[tid] = bc[tid];
    __syncthreads();

    const float* ksrc = kn + (size_t)img * 32 * HW;
    for (int i = tid; i < 32 * 14 * 8; i += 256) {
        int c = i / 112;
        int rem = i - c * 112;
        int r  = rem >> 3;
        int f4 = rem & 7;
        int gy = y0 - 3 + r;
        if (gy >= 0 && gy < 32) {
            float4 val = *(const float4*)(ksrc + (size_t)c * HW + gy * 32 + f4 * 4);
            float* dst = shk + c * KCH + r * KROW + 3 + f4 * 4;
            dst[0] = val.x; dst[1] = val.y; dst[2] = val.z; dst[3] = val.w;
        }
    }
    __syncthreads();

    const int tx = tid & 31;
    const int ty = tid >> 5;
    const int y  = y0 + ty;
    const int p  = y * 32 + tx;
    const int t    = img & 7;
    const int head = (img >> 3) & 7;
    const int b    = img >> 6;

    float q[32];
    {
        const float4* qv = (const float4*)(qn + ((size_t)img * HW + p) * 32);
#pragma unroll
        for (int i = 0; i < 8; i++) {
            float4 f = qv[i];
            q[i * 4 + 0] = f.x; q[i * 4 + 1] = f.y;
            q[i * 4 + 2] = f.z; q[i * 4 + 3] = f.w;
        }
    }
    float v[32];
#pragma unroll
    for (int e = 0; e < 32; e++) v[e] = 0.f;

    for (int dy = 0; dy < 7; dy++) {
        const int rb = (ty + dy) * KROW + tx;
#pragma unroll
        for (int dx = 0; dx < 7; dx++) {
            const float* kp = shk + rb + dx;
            float corr = 0.f;
#pragma unroll
            for (int c = 0; c < 32; c++) corr += q[c] * kp[c * KCH];
            const float4* wv = (const float4*)(shw + (dy * 7 + dx) * 32);
#pragma unroll
            for (int e = 0; e < 8; e++) {
                float4 ww = wv[e];
                v[e * 4 + 0] += corr * ww.x;
                v[e * 4 + 1] += corr * ww.y;
                v[e * 4 + 2] += corr * ww.z;
                v[e * 4 + 3] += corr * ww.w;
            }
        }
    }

    size_t base = ((size_t)b * N_ + t * HW + p) * C_ + head * 32;
    uint32_t hw[16], lw[16];
#pragma unroll
    for (int e2 = 0; e2 < 16; e2++) {
        float o0 = v[2 * e2 + 0] + shb[2 * e2 + 0];
        float o1 = v[2 * e2 + 1] + shb[2 * e2 + 1];
        __nv_bfloat162 hb = __floats2bfloat162_rn(o0, o1);
        float r0 = o0 - __bfloat162float(__low2bfloat16(hb));
        float r1 = o1 - __bfloat162float(__high2bfloat16(hb));
        __nv_bfloat162 lb = __floats2bfloat162_rn(r0, r1);
        hw[e2] = *(uint32_t*)&hb;
        lw[e2] = *(uint32_t*)&lb;
    }
#pragma unroll
    for (int s = 0; s < 4; s++) {
        *(uint4*)(vhi + base + s * 8) = make_uint4(hw[4*s], hw[4*s+1], hw[4*s+2], hw[4*s+3]);
        *(uint4*)(vlo + base + s * 8) = make_uint4(lw[4*s], lw[4*s+1], lw[4*s+2], lw[4*s+3]);
    }
}

// =================================================================================
extern "C" void kernel_launch(void* const* d_in, const int* in_sizes, int n_in,
                              void* d_out, int out_size)
{
    const float* x      = (const float*)d_in[0];
    const float* w_qk   = (const float*)d_in[1];
    const float* w_corr = (const float*)d_in[2];
    const float* b_corr = (const float*)d_in[3];
    const float* w_proj = (const float*)d_in[4];
    const float* b_proj = (const float*)d_in[5];
    float* out = (float*)d_out;

    float *qn, *kn;
    __nv_bfloat16 *xhi, *xlo, *vhi, *vlo, *wqh, *wql, *wph, *wpl;
    cudaGetSymbolAddress((void**)&qn,  g_qn);
    cudaGetSymbolAddress((void**)&kn,  g_kn);
    cudaGetSymbolAddress((void**)&xhi, g_xhi);
    cudaGetSymbolAddress((void**)&xlo, g_xlo);
    cudaGetSymbolAddress((void**)&vhi, g_vhi);
    cudaGetSymbolAddress((void**)&vlo, g_vlo);
    cudaGetSymbolAddress((void**)&wqh, g_wqk_hi);
    cudaGetSymbolAddress((void**)&wql, g_wqk_lo);
    cudaGetSymbolAddress((void**)&wph, g_wpj_hi);
    cudaGetSymbolAddress((void**)&wpl, g_wpj_lo);

    cudaFuncSetAttribute(gemm_qk,   cudaFuncAttributeMaxDynamicSharedMemorySize, GM_SMEM);
    cudaFuncSetAttribute(gemm_proj, cudaFuncAttributeMaxDynamicSharedMemorySize, GM_SMEM);
    cudaFuncSetAttribute(corr_kernel, cudaFuncAttributeMaxDynamicSharedMemorySize,
                         CORR_SMEM_BYTES);

    // 0) hi/lo splits
    conv_split<<<(M_TOT * C_ / 4 + 255) / 256, 256>>>((const float4*)x, (uint2*)xhi, (uint2*)xlo, M_TOT * C_ / 4);
    conv_split<<<(512 * 256 / 4 + 255) / 256, 256>>>((const float4*)w_qk, (uint2*)wqh, (uint2*)wql, 512 * 256 / 4);
    conv_split<<<(256 * 256 / 4 + 255) / 256, 256>>>((const float4*)w_proj, (uint2*)wph, (uint2*)wpl, 256 * 256 / 4);

    // 1) qk GEMM fused with normalize + temporal shift + relayout
    gemm_qk<<<dim3(4, 512), 256, GM_SMEM>>>(xhi, xlo, wqh, wql, qn, kn);

    // 2) fused 7x7 correlation + w_corr projection -> v (bf16 hi/lo)
    corr_kernel<<<BHT * 4, 256, CORR_SMEM_BYTES>>>(qn, kn, w_corr, b_corr, vhi, vlo);

    // 3) out = v @ w_proj^T + b_proj
    gemm_proj<<<dim3(2, 512), 256, GM_SMEM>>>(vhi, vlo, wph, wpl, b_proj, out, 256);
}

// round 5
// speedup vs baseline: 1.8958x; 1.0438x over previous
#include <cuda_runtime.h>
#include <cuda_bf16.h>
#include <math.h>
#include <stdint.h>

#define B_    8
#define NH    8
#define T_    8
#define HD    32
#define C_    256
#define N_    8192
#define HW    1024
#define BHT   512            // B*NH*T
#define M_TOT 65536          // B*N

// ---------------- scratch (static device globals; no allocation) ----------------
__device__ float g_qn[(size_t)BHT * HW * HD];          //  67 MB : normalized q [bht][p][c]
__device__ float g_kn[(size_t)BHT * HD * HW];          //  67 MB : normalized shifted k [bht][c][p]
__device__ __nv_bfloat16 g_xhi[(size_t)M_TOT * C_];    //  34 MB
__device__ __nv_bfloat16 g_xlo[(size_t)M_TOT * C_];
__device__ __nv_bfloat16 g_vhi[(size_t)M_TOT * C_];
__device__ __nv_bfloat16 g_vlo[(size_t)M_TOT * C_];
__device__ __nv_bfloat16 g_wqk_hi[512 * 256];
__device__ __nv_bfloat16 g_wqk_lo[512 * 256];
__device__ __nv_bfloat16 g_wpj_hi[256 * 256];
__device__ __nv_bfloat16 g_wpj_lo[256 * 256];

// ======================= asm helpers (sm_80-base features only) ==================
__device__ __forceinline__ uint32_t smem_u32(const void* p) {
    uint32_t a;
    asm("{ .reg .u64 t; cvta.to.shared.u64 t, %1; cvt.u32.u64 %0, t; }" : "=r"(a) : "l"(p));
    return a;
}
__device__ __forceinline__ void cp16(uint32_t saddr, const void* g) {
    asm volatile("cp.async.cg.shared.global [%0], [%1], 16;" :: "r"(saddr), "l"(g));
}
#define CP_COMMIT() asm volatile("cp.async.commit_group;" ::: "memory")
#define CP_WAIT1()  asm volatile("cp.async.wait_group 1;" ::: "memory")

#define LDSM4(r0, r1, r2, r3, addr) \
    asm volatile("ldmatrix.sync.aligned.m8n8.x4.shared.b16 {%0,%1,%2,%3}, [%4];" \
                 : "=r"(r0), "=r"(r1), "=r"(r2), "=r"(r3) : "r"(addr))
#define MMA16816(c, a, b0, b1) \
    asm volatile("mma.sync.aligned.m16n8k16.row.col.f32.bf16.bf16.f32 " \
                 "{%0,%1,%2,%3},{%4,%5,%6,%7},{%8,%9},{%0,%1,%2,%3};" \
                 : "+f"((c)[0]), "+f"((c)[1]), "+f"((c)[2]), "+f"((c)[3]) \
                 : "r"((a)[0]), "r"((a)[1]), "r"((a)[2]), "r"((a)[3]), \
                   "r"(b0), "r"(b1))

// =================================================================================
// fp32 -> (bf16 hi, bf16 lo) split, vectorized
// =================================================================================
__global__ void __launch_bounds__(256)
conv_split(const float4* __restrict__ in, uint2* __restrict__ hi,
           uint2* __restrict__ lo, int n4)
{
    int i = blockIdx.x * 256 + threadIdx.x;
    if (i >= n4) return;
    float4 f = in[i];
    __nv_bfloat162 h0 = __floats2bfloat162_rn(f.x, f.y);
    __nv_bfloat162 h1 = __floats2bfloat162_rn(f.z, f.w);
    float r0 = f.x - __bfloat162float(__low2bfloat16(h0));
    float r1 = f.y - __bfloat162float(__high2bfloat16(h0));
    float r2 = f.z - __bfloat162float(__low2bfloat16(h1));
    float r3 = f.w - __bfloat162float(__high2bfloat16(h1));
    __nv_bfloat162 l0 = __floats2bfloat162_rn(r0, r1);
    __nv_bfloat162 l1 = __floats2bfloat162_rn(r2, r3);
    hi[i] = make_uint2(*(uint32_t*)&h0, *(uint32_t*)&h1);
    lo[i] = make_uint2(*(uint32_t*)&l0, *(uint32_t*)&l1);
}

// =================================================================================
// Shared GEMM machinery: block 128x128, 256 thr, warp tile 64x32, BK=32,
// 3-stage cp.async pipeline, K=256 fixed (NT=8). 3-term bf16:
//   Ahi*Bhi + Ahi*Blo + Alo*Bhi, with B hi+lo fetched in ONE LDSM4.
// =================================================================================
#define KGEMM 256
#define NTILES 8
#define GM_STAGE 32768
#define GM_SMEM  (3 * GM_STAGE)

__device__ __forceinline__ void stage_load(
    uint32_t sbase, const __nv_bfloat16* __restrict__ Ahi,
    const __nv_bfloat16* __restrict__ Alo, const __nv_bfloat16* __restrict__ Bhi,
    const __nv_bfloat16* __restrict__ Blo, int m0, int n0, int kt, int tid)
{
    int t = tid * 2;
    int row = t >> 2;
    int cb  = t & 3;
#pragma unroll
    for (int j = 0; j < 2; j++) {
        int c16 = cb + j;
        uint32_t soff = (uint32_t)(row * 64 + ((c16 ^ ((row >> 1) & 3)) << 4));
        size_t ga = (size_t)row * KGEMM + kt * 32 + c16 * 8;
        cp16(sbase +     0 + soff, Ahi + (size_t)m0 * KGEMM + ga);
        cp16(sbase +  8192 + soff, Alo + (size_t)m0 * KGEMM + ga);
        cp16(sbase + 16384 + soff, Bhi + (size_t)n0 * KGEMM + ga);
        cp16(sbase + 24576 + soff, Blo + (size_t)n0 * KGEMM + ga);
    }
}

__device__ __forceinline__ void gemm_mainloop(
    const __nv_bfloat16* __restrict__ Ahi, const __nv_bfloat16* __restrict__ Alo,
    const __nv_bfloat16* __restrict__ Bhi, const __nv_bfloat16* __restrict__ Blo,
    uint32_t sb, int m0, int n0, int tid, int lane, int wm, int wn,
    float acc[4][4][4])
{
#pragma unroll
    for (int i = 0; i < 4; i++)
#pragma unroll
        for (int j = 0; j < 4; j++)
#pragma unroll
            for (int q = 0; q < 4; q++) acc[i][j][q] = 0.f;

    stage_load(sb,            Ahi, Alo, Bhi, Blo, m0, n0, 0, tid);
    CP_COMMIT();
    stage_load(sb + GM_STAGE, Ahi, Alo, Bhi, Blo, m0, n0, 1, tid);
    CP_COMMIT();

    const uint32_t l2 = lane & 15;
    const uint32_t bsel = (lane & 16) ? 8192u : 0u;   // lanes 16-31 fetch B_lo rows

    int stage = 0;
    int lstage = 2;
    for (int kt = 0; kt < NTILES; kt++) {
        CP_WAIT1();
        __syncthreads();
        if (kt + 2 < NTILES)
            stage_load(sb + lstage * GM_STAGE, Ahi, Alo, Bhi, Blo, m0, n0, kt + 2, tid);
        CP_COMMIT();
        lstage = stage;

        const uint32_t sa = sb + stage * GM_STAGE;
        stage = (stage == 2) ? 0 : stage + 1;

#pragma unroll
        for (int ks = 0; ks < 2; ks++) {
            uint32_t aaddr[4], baddr[4];
            {
                uint32_t achk = (uint32_t)(ks * 2) + (lane >> 4);
#pragma unroll
                for (int i = 0; i < 4; i++) {
                    uint32_t r = wm + l2 + i * 16;
                    aaddr[i] = sa + r * 64 + ((achk ^ ((r >> 1) & 3)) << 4);
                }
                uint32_t bchk = (uint32_t)(ks * 2) + ((l2 >> 3) & 1);
#pragma unroll
                for (int j = 0; j < 4; j++) {
                    uint32_t r = wn + (l2 & 7) + j * 8;
                    baddr[j] = sa + 16384 + r * 64 + ((bchk ^ ((r >> 1) & 3)) << 4) + bsel;
                }
            }
            uint32_t a[4][4], al[4][4], b4[4][4];
#pragma unroll
            for (int i = 0; i < 4; i++) LDSM4(a[i][0], a[i][1], a[i][2], a[i][3], aaddr[i]);
#pragma unroll
            for (int j = 0; j < 4; j++) LDSM4(b4[j][0], b4[j][1], b4[j][2], b4[j][3], baddr[j]);
#pragma unroll
            for (int i = 0; i < 4; i++) LDSM4(al[i][0], al[i][1], al[i][2], al[i][3], aaddr[i] + 8192);
            // term 1: Ahi*Bhi
#pragma unroll
            for (int i = 0; i < 4; i++)
#pragma unroll
                for (int j = 0; j < 4; j++) MMA16816(acc[i][j], a[i], b4[j][0], b4[j][1]);
            // term 3: Ahi*Blo
#pragma unroll
            for (int i = 0; i < 4; i++)
#pragma unroll
                for (int j = 0; j < 4; j++) MMA16816(acc[i][j], a[i], b4[j][2], b4[j][3]);
            // term 2: Alo*Bhi
#pragma unroll
            for (int i = 0; i < 4; i++)
#pragma unroll
                for (int j = 0; j < 4; j++) MMA16816(acc[i][j], al[i], b4[j][0], b4[j][1]);
        }
    }
}

// =================================================================================
// GEMM1 fused: qk = x @ w_qk^T, then per-(row,head) L2-normalize + temporal shift,
// writing qn (channel-last) and kn (channel-first, shifted).
// =================================================================================
__global__ void __launch_bounds__(256, 2)
gemm_qk(const __nv_bfloat16* __restrict__ Ahi, const __nv_bfloat16* __restrict__ Alo,
        const __nv_bfloat16* __restrict__ Bhi, const __nv_bfloat16* __restrict__ Blo,
        float* __restrict__ qn, float* __restrict__ kn)
{
    extern __shared__ char smg[];
    const uint32_t sb = smem_u32(smg);
    const int tid = threadIdx.x;
    const int lane = tid & 31;
    const int wid = tid >> 5;
    const int m0 = blockIdx.y * 128;
    const int n0 = blockIdx.x * 128;
    const int wm = (wid >> 2) * 64;
    const int wn = (wid & 3) * 32;

    float acc[4][4][4];
    gemm_mainloop(Ahi, Alo, Bhi, Blo, sb, m0, n0, tid, lane, wm, wn, acc);

    const bool is_k = (blockIdx.x >= 2);
    const int head = (((n0 & 255) + wn) >> 5);

#pragma unroll
    for (int i = 0; i < 4; i++) {
#pragma unroll
        for (int h = 0; h < 2; h++) {
            float v0[4], v1[4];
            float ss = 0.f;
#pragma unroll
            for (int j = 0; j < 4; j++) {
                v0[j] = acc[i][j][2 * h];
                v1[j] = acc[i][j][2 * h + 1];
                ss += v0[j] * v0[j] + v1[j] * v1[j];
            }
            ss += __shfl_xor_sync(0xffffffffu, ss, 1);
            ss += __shfl_xor_sync(0xffffffffu, ss, 2);
            float inv = 1.0f / fmaxf(sqrtf(ss), 1e-12f);

            int r = m0 + wm + i * 16 + (lane >> 2) + h * 8;
            int b  = r >> 13;
            int tt = (r >> 10) & 7;
            int p  = r & 1023;

            if (!is_k) {
                int bht = b * 64 + head * 8 + tt;
                float* dst = qn + ((size_t)bht * HW + p) * 32;
#pragma unroll
                for (int j = 0; j < 4; j++) {
                    int cin = j * 8 + (lane & 3) * 2;
                    *(float2*)(dst + cin) = make_float2(v0[j] * inv, v1[j] * inv);
                }
            } else {
                if (tt >= 1) {
                    int bht = b * 64 + head * 8 + (tt - 1);
                    float* dst = kn + (size_t)bht * 32 * HW + p;
#pragma unroll
                    for (int j = 0; j < 4; j++) {
                        int cin = j * 8 + (lane & 3) * 2;
                        dst[(size_t)cin * HW]       = v0[j] * inv;
                        dst[(size_t)(cin + 1) * HW] = v1[j] * inv;
                    }
                }
                if (tt == 7) {
                    int bht = b * 64 + head * 8 + 7;
                    float* dst = kn + (size_t)bht * 32 * HW + p;
#pragma unroll
                    for (int j = 0; j < 4; j++) {
                        int cin = j * 8 + (lane & 3) * 2;
                        dst[(size_t)cin * HW]       = v0[j] * inv;
                        dst[(size_t)(cin + 1) * HW] = v1[j] * inv;
                    }
                }
            }
        }
    }
}

// =================================================================================
// GEMM4: out = v @ w_proj^T + bias, fp32 out
// =================================================================================
__global__ void __launch_bounds__(256, 2)
gemm_proj(const __nv_bfloat16* __restrict__ Ahi, const __nv_bfloat16* __restrict__ Alo,
          const __nv_bfloat16* __restrict__ Bhi, const __nv_bfloat16* __restrict__ Blo,
          const float* __restrict__ bias, float* __restrict__ C, int ldc)
{
    extern __shared__ char smg[];
    const uint32_t sb = smem_u32(smg);
    const int tid = threadIdx.x;
    const int lane = tid & 31;
    const int wid = tid >> 5;
    const int m0 = blockIdx.y * 128;
    const int n0 = blockIdx.x * 128;
    const int wm = (wid >> 2) * 64;
    const int wn = (wid & 3) * 32;

    float acc[4][4][4];
    gemm_mainloop(Ahi, Alo, Bhi, Blo, sb, m0, n0, tid, lane, wm, wn, acc);

#pragma unroll
    for (int j = 0; j < 4; j++) {
        int c = n0 + wn + j * 8 + (lane & 3) * 2;
        float b0 = bias[c], b1 = bias[c + 1];
#pragma unroll
        for (int i = 0; i < 4; i++) {
            int r = m0 + wm + i * 16 + (lane >> 2);
            *(float2*)(C + (size_t)r * ldc + c) =
                make_float2(acc[i][j][0] + b0, acc[i][j][1] + b1);
            *(float2*)(C + (size_t)(r + 8) * ldc + c) =
                make_float2(acc[i][j][2] + b0, acc[i][j][3] + b1);
        }
    }
}

// =================================================================================
// Fused 7x7 correlation + (49->32) projection.
// k tile in smem with CHANNEL PAIRS interleaved: shk2[cpair][row][col] = float2
// holding channels (2cp, 2cp+1) -> every tap load is one LDS.64 feeding 2 ch.
// Quarter-image blocks (8 rows), 256 thr, 1 px/thread.
// =================================================================================
#define KCOLS 38
#define KROWS 14
#define KCH2  (KROWS * KCOLS)                     // 532 float2 per cpair
#define CORR_SMEM_BYTES (16 * KCH2 * 8 + 49 * 16 * 8 + 128)   // 74496

__global__ void __launch_bounds__(256, 2)
corr_kernel(const float* __restrict__ qn, const float* __restrict__ kn,
            const float* __restrict__ wc, const float* __restrict__ bc,
            __nv_bfloat16* __restrict__ vhi, __nv_bfloat16* __restrict__ vlo)
{
    extern __shared__ float2 sh2[];
    float2* shk2 = sh2;                      // [16][14][38]
    float2* shw2 = sh2 + 16 * KCH2;          // [49][16] : (w[2e][j], w[2e+1][j])
    float*  shb  = (float*)(shw2 + 49 * 16); // 32

    const int tid = threadIdx.x;
    const int img = blockIdx.x >> 2;
    const int yq  = (blockIdx.x & 3) * 8;

    for (int i = tid; i < 16 * KCH2; i += 256) shk2[i] = make_float2(0.f, 0.f);
    for (int i = tid; i < 49 * 16; i += 256) {
        int j = i >> 4, e2 = i & 15;
        shw2[i] = make_float2(wc[(2 * e2) * 49 + j], wc[(2 * e2 + 1) * 49 + j]);
    }
    if (tid < 32) shb[tid] = bc[tid];
    __syncthreads();

    // fill valid k rows, interleaving channel pairs
    const float* ksrc = kn + (size_t)img * 32 * HW;
    for (int i = tid; i < 32 * 14 * 8; i += 256) {
        int c = i / 112, rem = i - (i / 112) * 112;
        int r = rem >> 3, x4 = rem & 7;
        int gy = yq - 3 + r;
        if (gy >= 0 && gy < 32) {
            float4 v = *(const float4*)(ksrc + (size_t)c * HW + gy * 32 + x4 * 4);
            float* base = (float*)(shk2 + (c >> 1) * KCH2 + r * KCOLS + 3 + x4 * 4) + (c & 1);
            base[0] = v.x; base[2] = v.y; base[4] = v.z; base[6] = v.w;
        }
    }
    __syncthreads();

    const int tx = tid & 31;
    const int ty = tid >> 5;
    const int p  = (yq + ty) * 32 + tx;
    const int t    = img & 7;
    const int head = (img >> 3) & 7;
    const int b    = img >> 6;

    float2 q2[16];
    {
        const float4* qv = (const float4*)(qn + ((size_t)img * HW + p) * 32);
#pragma unroll
        for (int i = 0; i < 8; i++) {
            float4 f = qv[i];
            q2[2 * i]     = make_float2(f.x, f.y);
            q2[2 * i + 1] = make_float2(f.z, f.w);
        }
    }
    float2 v2[16];
#pragma unroll
    for (int e = 0; e < 16; e++) v2[e] = make_float2(0.f, 0.f);

#pragma unroll 1
    for (int dy = 0; dy < 7; dy++) {
        float2 cA[7];
#pragma unroll
        for (int d = 0; d < 7; d++) cA[d] = make_float2(0.f, 0.f);
        const float2* base = shk2 + (ty + dy) * KCOLS + tx;
#pragma unroll
        for (int cp = 0; cp < 16; cp++) {
            const float2* bp = base + cp * KCH2;
            float2 qa = q2[cp];
#pragma unroll
            for (int dx = 0; dx < 7; dx++) {
                float2 kv = bp[dx];
                cA[dx].x += qa.x * kv.x;
                cA[dx].y += qa.y * kv.y;
            }
        }
#pragma unroll
        for (int dx = 0; dx < 7; dx++) {
            float s = cA[dx].x + cA[dx].y;
            const float4* wr = (const float4*)(shw2 + (dy * 7 + dx) * 16);
#pragma unroll
            for (int e4 = 0; e4 < 8; e4++) {
                float4 w4 = wr[e4];
                v2[2 * e4].x     += s * w4.x;
                v2[2 * e4].y     += s * w4.y;
                v2[2 * e4 + 1].x += s * w4.z;
                v2[2 * e4 + 1].y += s * w4.w;
            }
        }
    }

    size_t gbase = ((size_t)b * N_ + t * HW + p) * C_ + head * 32;
    uint32_t hw[16], lw[16];
#pragma unroll
    for (int e2 = 0; e2 < 16; e2++) {
        float o0 = v2[e2].x + shb[2 * e2 + 0];
        float o1 = v2[e2].y + shb[2 * e2 + 1];
        __nv_bfloat162 hb = __floats2bfloat162_rn(o0, o1);
        float r0 = o0 - __bfloat162float(__low2bfloat16(hb));
        float r1 = o1 - __bfloat162float(__high2bfloat16(hb));
        __nv_bfloat162 lb = __floats2bfloat162_rn(r0, r1);
        hw[e2] = *(uint32_t*)&hb;
        lw[e2] = *(uint32_t*)&lb;
    }
#pragma unroll
    for (int s = 0; s < 4; s++) {
        *(uint4*)(vhi + gbase + s * 8) = make_uint4(hw[4*s], hw[4*s+1], hw[4*s+2], hw[4*s+3]);
        *(uint4*)(vlo + gbase + s * 8) = make_uint4(lw[4*s], lw[4*s+1], lw[4*s+2], lw[4*s+3]);
    }
}

// =================================================================================
extern "C" void kernel_launch(void* const* d_in, const int* in_sizes, int n_in,
                              void* d_out, int out_size)
{
    const float* x      = (const float*)d_in[0];
    const float* w_qk   = (const float*)d_in[1];
    const float* w_corr = (const float*)d_in[2];
    const float* b_corr = (const float*)d_in[3];
    const float* w_proj = (const float*)d_in[4];
    const float* b_proj = (const float*)d_in[5];
    float* out = (float*)d_out;

    float *qn, *kn;
    __nv_bfloat16 *xhi, *xlo, *vhi, *vlo, *wqh, *wql, *wph, *wpl;
    cudaGetSymbolAddress((void**)&qn,  g_qn);
    cudaGetSymbolAddress((void**)&kn,  g_kn);
    cudaGetSymbolAddress((void**)&xhi, g_xhi);
    cudaGetSymbolAddress((void**)&xlo, g_xlo);
    cudaGetSymbolAddress((void**)&vhi, g_vhi);
    cudaGetSymbolAddress((void**)&vlo, g_vlo);
    cudaGetSymbolAddress((void**)&wqh, g_wqk_hi);
    cudaGetSymbolAddress((void**)&wql, g_wqk_lo);
    cudaGetSymbolAddress((void**)&wph, g_wpj_hi);
    cudaGetSymbolAddress((void**)&wpl, g_wpj_lo);

    cudaFuncSetAttribute(gemm_qk,   cudaFuncAttributeMaxDynamicSharedMemorySize, GM_SMEM);
    cudaFuncSetAttribute(gemm_proj, cudaFuncAttributeMaxDynamicSharedMemorySize, GM_SMEM);
    cudaFuncSetAttribute(corr_kernel, cudaFuncAttributeMaxDynamicSharedMemorySize,
                         CORR_SMEM_BYTES);

    // 0) hi/lo splits
    conv_split<<<(M_TOT * C_ / 4 + 255) / 256, 256>>>((const float4*)x, (uint2*)xhi, (uint2*)xlo, M_TOT * C_ / 4);
    conv_split<<<(512 * 256 / 4 + 255) / 256, 256>>>((const float4*)w_qk, (uint2*)wqh, (uint2*)wql, 512 * 256 / 4);
    conv_split<<<(256 * 256 / 4 + 255) / 256, 256>>>((const float4*)w_proj, (uint2*)wph, (uint2*)wpl, 256 * 256 / 4);

    // 1) qk GEMM fused with normalize + temporal shift + relayout
    gemm_qk<<<dim3(4, 512), 256, GM_SMEM>>>(xhi, xlo, wqh, wql, qn, kn);

    // 2) fused 7x7 correlation + w_corr projection -> v (bf16 hi/lo)
    corr_kernel<<<BHT * 4, 256, CORR_SMEM_BYTES>>>(qn, kn, w_corr, b_corr, vhi, vlo);

    // 3) out = v @ w_proj^T + b_proj
    gemm_proj<<<dim3(2, 512), 256, GM_SMEM>>>(vhi, vlo, wph, wpl, b_proj, out, 256);
}